// round 7
// baseline (speedup 1.0000x reference)
#include <cuda_runtime.h>
#include <cuda_fp16.h>
#include <cstdint>

// Y = X @ (W_nf4 * c1 * c_kbit_2) + (X@L1)@L2
// Folded-K: Xe fp16 [8192,4160]=[X | X@L1 | 0], We fp16 [4096,4160]=[W^T | L2^T | 0]
// GEMM via mma.sync.m16n8k16 (tcgen05 rejected at plain sm_103 PTX target).
// R6->R7: (a) issue the prefetched ks=0 MMA block BEFORE __syncthreads so the
// barrier drains under queued tensor work; (b) fuse the 3 independent pack
// kernels into one grid (concurrent execution, 2 fewer launches).

static constexpr int D_IN  = 4096;
static constexpr int D_OUT = 4096;
static constexpr int NROWS = 8192;
static constexpr int KPAD  = 4160;

static constexpr int BM = 128, BN = 128, BK = 64, S = 3;
static constexpr int KT = KPAD / BK;              // 65
static constexpr int ABYTES = BM * BK * 2;        // 16384
static constexpr int BBYTES = BN * BK * 2;        // 16384
static constexpr int STAGE  = ABYTES + BBYTES;    // 32768
static constexpr int SMEM_SZ = S * STAGE;         // 98304 (2 CTAs/SM)

// fused pack grid layout
static constexpr int PX_BLOCKS = NROWS / 32;                  // 256
static constexpr int PW_BLOCKS = (D_OUT / 64) * (D_IN / 64);  // 4096
static constexpr int PT_BLOCKS = (D_OUT * 64) / 256;          // 1024
static constexpr int PACK_BLOCKS = PX_BLOCKS + PW_BLOCKS + PT_BLOCKS;

__device__ __align__(16) __half g_Xe[(size_t)NROWS * KPAD];   // 68 MB
__device__ __align__(16) __half g_We[(size_t)D_OUT * KPAD];   // 34 MB

// ------------------------------ PTX helpers -------------------------------
__device__ __forceinline__ void cp16(uint32_t dst, const void* src) {
    asm volatile("cp.async.cg.shared.global [%0], [%1], 16;"
                 :: "r"(dst), "l"(__cvta_generic_to_global(src)) : "memory");
}
#define CP_COMMIT() asm volatile("cp.async.commit_group;" ::: "memory")
#define CP_WAIT(n)  asm volatile("cp.async.wait_group %0;" :: "n"(n) : "memory")

#define LDSM4(r, a) \
    asm volatile("ldmatrix.sync.aligned.m8n8.x4.shared.b16 {%0,%1,%2,%3}, [%4];" \
        : "=r"((r)[0]), "=r"((r)[1]), "=r"((r)[2]), "=r"((r)[3]) : "r"(a))

#define MMA16816(d, a, b) \
    asm volatile("mma.sync.aligned.m16n8k16.row.col.f32.f16.f16.f32 " \
        "{%0,%1,%2,%3}, {%4,%5,%6,%7}, {%8,%9}, {%0,%1,%2,%3};" \
        : "+f"((d)[0]), "+f"((d)[1]), "+f"((d)[2]), "+f"((d)[3]) \
        : "r"((a)[0]), "r"((a)[1]), "r"((a)[2]), "r"((a)[3]), \
          "r"((b)[0]), "r"((b)[1]))

__device__ __forceinline__ uint32_t swz(uint32_t o) { return o ^ ((o >> 3) & 0x70); }

// --------------------------- fused pack kernel -----------------------------
// blocks [0, 256): pack_x (32 rows each: fp16(X) + X@L1 -> Xe)
// blocks [256, 4352): pack_w (64x64 dequant+transpose tile -> We)
// blocks [4352, 5376): pack_tail (L2 rows + zero pad -> We cols 4096..4159)
__global__ void __launch_bounds__(256)
pack_kernel(const float* __restrict__ X,  const float* __restrict__ Wq,
            const float* __restrict__ c1p, const float* __restrict__ ck,
            const float* __restrict__ L1, const float* __restrict__ L2) {
    __shared__ union {
        float sL1[512 * 17];     // 34816 B
        float tile[64 * 65];     // 16640 B
    } sm;

    const int bid = blockIdx.x;
    const int tid = threadIdx.x;

    if (bid < PX_BLOCKS) {
        // ---------------- pack_x ----------------
        const int lane = tid & 31, warp = tid >> 5;
        const int rowbase = bid * 32 + warp * 4;

        float acc[4][16];
#pragma unroll
        for (int r = 0; r < 4; r++)
#pragma unroll
            for (int j = 0; j < 16; j++) acc[r][j] = 0.f;

        for (int ch = 0; ch < 8; ch++) {
            const int k0 = ch * 512;
#pragma unroll
            for (int i = 0; i < 32; i++) {
                int idx = tid + i * 256;
                int kk = idx >> 4, j = idx & 15;
                sm.sL1[kk * 17 + j] = L1[(size_t)(k0 + kk) * 16 + j];
            }
            __syncthreads();

#pragma unroll 4
            for (int ii = 0; ii < 16; ii++) {
                const int kk = ii * 32 + lane;
                const int k  = k0 + kk;
                float xs[4];
#pragma unroll
                for (int r = 0; r < 4; r++) {
                    float v = X[(size_t)(rowbase + r) * D_IN + k];
                    xs[r] = v;
                    g_Xe[(size_t)(rowbase + r) * KPAD + k] = __float2half_rn(v);
                }
                const float* lp = sm.sL1 + kk * 17;
#pragma unroll
                for (int j = 0; j < 16; j++) {
                    float lv = lp[j];
#pragma unroll
                    for (int r = 0; r < 4; r++) acc[r][j] += xs[r] * lv;
                }
            }
            __syncthreads();
        }

#pragma unroll
        for (int r = 0; r < 4; r++) {
#pragma unroll
            for (int j = 0; j < 16; j++) {
                float v = acc[r][j];
                v += __shfl_xor_sync(0xffffffffu, v, 16);
                v += __shfl_xor_sync(0xffffffffu, v, 8);
                v += __shfl_xor_sync(0xffffffffu, v, 4);
                v += __shfl_xor_sync(0xffffffffu, v, 2);
                v += __shfl_xor_sync(0xffffffffu, v, 1);
                acc[r][j] = v;
            }
            const int row = rowbase + r;
            if (lane == 0) {
#pragma unroll
                for (int j = 0; j < 16; j++)
                    g_Xe[(size_t)row * KPAD + 4096 + j] = __float2half_rn(acc[r][j]);
            }
            if (lane < 6)
                *(uint4*)(g_Xe + (size_t)row * KPAD + 4112 + (size_t)lane * 8) =
                    make_uint4(0, 0, 0, 0);
        }
    } else if (bid < PX_BLOCKS + PW_BLOCKS) {
        // ---------------- pack_w ----------------
        const int b = bid - PX_BLOCKS;
        const float c1 = *c1p;
        const int n0 = (b & 63) * 64, k0 = (b >> 6) * 64;
        const int cidx = tid & 63, ridx = tid >> 6;

#pragma unroll
        for (int ro = 0; ro < 16; ro++) {
            int kk = ro * 4 + ridx;
            size_t g = (size_t)(k0 + kk) * D_OUT + n0 + cidx;
            sm.tile[kk * 65 + cidx] = Wq[g] * c1 * ck[g];
        }
        __syncthreads();
#pragma unroll
        for (int ro = 0; ro < 16; ro++) {
            int nn = ro * 4 + ridx;
            g_We[(size_t)(n0 + nn) * KPAD + k0 + cidx] =
                __float2half_rn(sm.tile[cidx * 65 + nn]);
        }
    } else {
        // ---------------- pack_tail ----------------
        const int b = bid - PX_BLOCKS - PW_BLOCKS;
        int idx = b * 256 + tid;                 // 4096 * 64
        int n = idx >> 6, kk = idx & 63;
        __half v = (kk < 16) ? __float2half_rn(L2[(size_t)kk * D_OUT + n])
                             : __half(0.f);
        g_We[(size_t)n * KPAD + 4096 + kk] = v;
    }
}

// ------------------------------ GEMM kernel --------------------------------
// 128 threads = 4 warps (2x2), warp tile 64x64, cross-iteration frag prefetch.
// ks=0 MMA block issues BEFORE the barrier (reads prefetched regs only), so
// the barrier + first LDSM chain drain under queued tensor-pipe work.
__global__ void __launch_bounds__(128, 2)
gemm_kernel(float* __restrict__ Y) {
    extern __shared__ char smem[];
    const uint32_t sb = (uint32_t)__cvta_generic_to_shared(smem);
    const int tid = threadIdx.x, wid = tid >> 5, lane = tid & 31;
    const int m0 = blockIdx.y * BM, n0 = blockIdx.x * BN;
    const int wm = wid & 1, wn = wid >> 1;
    const int gid = lane >> 2, tig = lane & 3;

    auto loadA = [&](int kt, int slot) {
        const __half* src = g_Xe + (size_t)m0 * KPAD + (size_t)kt * BK;
        uint32_t base = sb + slot * STAGE;
#pragma unroll
        for (int i = 0; i < 8; i++) {
            int idx = tid + i * 128;
            int r = idx >> 3, c = idx & 7;
            cp16(base + swz((uint32_t)(r * 128 + c * 16)),
                 src + (size_t)r * KPAD + c * 8);
        }
    };
    auto loadB = [&](int kt, int slot) {
        const __half* src = g_We + (size_t)n0 * KPAD + (size_t)kt * BK;
        uint32_t base = sb + slot * STAGE + ABYTES;
#pragma unroll
        for (int i = 0; i < 8; i++) {
            int idx = tid + i * 128;
            int r = idx >> 3, c = idx & 7;
            cp16(base + swz((uint32_t)(r * 128 + c * 16)),
                 src + (size_t)r * KPAD + c * 8);
        }
    };

    float acc[4][8][4];
#pragma unroll
    for (int t = 0; t < 4; t++)
#pragma unroll
        for (int n = 0; n < 8; n++)
#pragma unroll
            for (int j = 0; j < 4; j++) acc[t][n][j] = 0.f;

    // Prologue: stages 0,1 committed as separate groups
#pragma unroll
    for (int s = 0; s < S - 1; s++) { loadA(s, s); loadB(s, s); CP_COMMIT(); }

    const uint32_t a_row = (uint32_t)(wm * 64 + (lane & 15));
    const uint32_t a_chk = (uint32_t)(lane >> 4);
    const uint32_t b_row = (uint32_t)(wn * 64 + ((lane >> 4) & 1) * 8 + (lane & 7));
    const uint32_t b_chk = (uint32_t)((lane >> 3) & 1);

    uint32_t af[2][4][4];
    uint32_t bf[2][8][2];

    auto load_frag = [&](int buf, uint32_t abase, int ks) {
        const uint32_t bbase = abase + ABYTES;
#pragma unroll
        for (int t = 0; t < 4; t++) {
            uint32_t off = (a_row + t * 16) * 128 + (a_chk + ks * 2) * 16;
            LDSM4(af[buf][t], abase + swz(off));
        }
#pragma unroll
        for (int g = 0; g < 4; g++) {
            uint32_t off = (b_row + g * 16) * 128 + (b_chk + ks * 2) * 16;
            uint32_t r[4];
            LDSM4(r, bbase + swz(off));
            bf[buf][2 * g][0] = r[0];     bf[buf][2 * g][1] = r[1];
            bf[buf][2 * g + 1][0] = r[2]; bf[buf][2 * g + 1][1] = r[3];
        }
    };
    auto mma_block = [&](int buf) {
#pragma unroll
        for (int t = 0; t < 4; t++)
#pragma unroll
            for (int n = 0; n < 8; n++)
                MMA16816(acc[t][n], af[buf][t], bf[buf][n]);
    };

    // Wait stage 0 (leave stage 1 in flight), prefetch its ks=0 fragments.
    CP_WAIT(1);
    __syncthreads();
    load_frag(0, sb + 0 * STAGE, 0);

    for (int kt = 0; kt < KT; kt++) {
        const uint32_t abase = sb + (kt % S) * STAGE;

        mma_block(0);                    // ks=0 (prefetched regs only) — queues
                                         // tensor work that drains through the
                                         // barrier + first LDSM chain below.
        // Barrier: about to overwrite slot (kt+2)%S == (kt-1)%S; all reads of
        // that slot finished last iteration.
        __syncthreads();

        load_frag(1, abase, 1);
        if (kt + 2 < KT) {               // issue next stage UNCOMMITTED
            loadA(kt + 2, (kt + 2) % S);
            loadB(kt + 2, (kt + 2) % S);
        }

        load_frag(0, abase, 2);
        mma_block(1);                    // ks=1

        load_frag(1, abase, 3);
        mma_block(0);                    // ks=2

        if (kt + 1 < KT) {
            CP_WAIT(0);                  // drains stage kt+1 only (kt+2 uncommitted)
            load_frag(0, sb + ((kt + 1) % S) * STAGE, 0);   // prefetch next ks=0
        }
        mma_block(1);                    // ks=3
        CP_COMMIT();                     // name stage kt+2's group
    }

    // Epilogue: direct float2 stores
#pragma unroll
    for (int t = 0; t < 4; t++) {
        const int r0 = m0 + wm * 64 + t * 16 + gid;
        float* y0 = Y + (size_t)r0 * D_OUT + n0 + wn * 64 + tig * 2;
        float* y1 = y0 + (size_t)8 * D_OUT;
#pragma unroll
        for (int n = 0; n < 8; n++) {
            *(float2*)(y0 + n * 8) = make_float2(acc[t][n][0], acc[t][n][1]);
            *(float2*)(y1 + n * 8) = make_float2(acc[t][n][2], acc[t][n][3]);
        }
    }
}

// ------------------------------- launcher ----------------------------------
extern "C" void kernel_launch(void* const* d_in, const int* in_sizes, int n_in,
                              void* d_out, int out_size) {
    const float* X  = (const float*)d_in[0];
    const float* Wq = (const float*)d_in[1];
    const float* c1 = (const float*)d_in[2];
    const float* ck = (const float*)d_in[3];
    const float* L1 = (const float*)d_in[4];
    const float* L2 = (const float*)d_in[5];
    float* Y = (float*)d_out;

    cudaFuncSetAttribute(gemm_kernel, cudaFuncAttributeMaxDynamicSharedMemorySize, SMEM_SZ);

    pack_kernel<<<PACK_BLOCKS, 256>>>(X, Wq, c1, ck, L1, L2);
    gemm_kernel<<<dim3(D_OUT / BN, NROWS / BM), 128, SMEM_SZ>>>(Y);
}

// round 8
// speedup vs baseline: 1.1865x; 1.1865x over previous
#include <cuda_runtime.h>
#include <cuda_fp16.h>
#include <cstdint>

// Y = X @ (W_nf4 * c1 * c_kbit_2) + (X@L1)@L2
// Folded-K: Xe fp16 [8192,4160]=[X | X@L1 | 0], We fp16 [4096,4160]=[W^T | L2^T | 0]
// GEMM via mma.sync.m16n8k16 (tcgen05 rejected at plain sm_103 PTX target).
// R7->R8: revert both R7 changes (pre-barrier MMA cost overlap; fused packs
// stretched pack_x). GEMM is exact R6 (536.8us, tensor 86.5%). Packs split
// again; pack_tail merged into pack_w's k0=4032 blocks; pack_x uses
// float2/half2 accesses for full-width stores.

static constexpr int D_IN  = 4096;
static constexpr int D_OUT = 4096;
static constexpr int NROWS = 8192;
static constexpr int KPAD  = 4160;

static constexpr int BM = 128, BN = 128, BK = 64, S = 3;
static constexpr int KT = KPAD / BK;              // 65
static constexpr int ABYTES = BM * BK * 2;        // 16384
static constexpr int BBYTES = BN * BK * 2;        // 16384
static constexpr int STAGE  = ABYTES + BBYTES;    // 32768
static constexpr int SMEM_SZ = S * STAGE;         // 98304 (2 CTAs/SM)

__device__ __align__(16) __half g_Xe[(size_t)NROWS * KPAD];   // 68 MB
__device__ __align__(16) __half g_We[(size_t)D_OUT * KPAD];   // 34 MB

// ------------------------------ PTX helpers -------------------------------
__device__ __forceinline__ void cp16(uint32_t dst, const void* src) {
    asm volatile("cp.async.cg.shared.global [%0], [%1], 16;"
                 :: "r"(dst), "l"(__cvta_generic_to_global(src)) : "memory");
}
#define CP_COMMIT() asm volatile("cp.async.commit_group;" ::: "memory")
#define CP_WAIT(n)  asm volatile("cp.async.wait_group %0;" :: "n"(n) : "memory")

#define LDSM4(r, a) \
    asm volatile("ldmatrix.sync.aligned.m8n8.x4.shared.b16 {%0,%1,%2,%3}, [%4];" \
        : "=r"((r)[0]), "=r"((r)[1]), "=r"((r)[2]), "=r"((r)[3]) : "r"(a))

#define MMA16816(d, a, b) \
    asm volatile("mma.sync.aligned.m16n8k16.row.col.f32.f16.f16.f32 " \
        "{%0,%1,%2,%3}, {%4,%5,%6,%7}, {%8,%9}, {%0,%1,%2,%3};" \
        : "+f"((d)[0]), "+f"((d)[1]), "+f"((d)[2]), "+f"((d)[3]) \
        : "r"((a)[0]), "r"((a)[1]), "r"((a)[2]), "r"((a)[3]), \
          "r"((b)[0]), "r"((b)[1]))

__device__ __forceinline__ uint32_t swz(uint32_t o) { return o ^ ((o >> 3) & 0x70); }

// ----------------------- pack_X: fp16(X) and X@L1 -------------------------
// Each lane handles 2 consecutive k per step: float2 load, __half2 store.
__global__ void __launch_bounds__(256, 2)
pack_x_kernel(const float* __restrict__ X, const float* __restrict__ L1) {
    __shared__ float sL1[512 * 17];
    const int tid = threadIdx.x, lane = tid & 31, warp = tid >> 5;
    const int rowbase = blockIdx.x * 32 + warp * 4;

    float acc[4][16];
#pragma unroll
    for (int r = 0; r < 4; r++)
#pragma unroll
        for (int j = 0; j < 16; j++) acc[r][j] = 0.f;

    for (int ch = 0; ch < 8; ch++) {
        const int k0 = ch * 512;
#pragma unroll
        for (int i = 0; i < 32; i++) {
            int idx = tid + i * 256;
            int kk = idx >> 4, j = idx & 15;
            sL1[kk * 17 + j] = L1[(size_t)(k0 + kk) * 16 + j];
        }
        __syncthreads();

#pragma unroll 2
        for (int ii = 0; ii < 8; ii++) {
            const int kk = ii * 64 + lane * 2;
            const int k  = k0 + kk;
            float x0[4], x1[4];
#pragma unroll
            for (int r = 0; r < 4; r++) {
                float2 v = *(const float2*)(X + (size_t)(rowbase + r) * D_IN + k);
                x0[r] = v.x; x1[r] = v.y;
                *(__half2*)(g_Xe + (size_t)(rowbase + r) * KPAD + k) =
                    __floats2half2_rn(v.x, v.y);
            }
            const float* lp0 = sL1 + kk * 17;
            const float* lp1 = lp0 + 17;
#pragma unroll
            for (int j = 0; j < 16; j++) {
                float l0 = lp0[j], l1 = lp1[j];
#pragma unroll
                for (int r = 0; r < 4; r++)
                    acc[r][j] += x0[r] * l0 + x1[r] * l1;
            }
        }
        __syncthreads();
    }

#pragma unroll
    for (int r = 0; r < 4; r++) {
#pragma unroll
        for (int j = 0; j < 16; j++) {
            float v = acc[r][j];
            v += __shfl_xor_sync(0xffffffffu, v, 16);
            v += __shfl_xor_sync(0xffffffffu, v, 8);
            v += __shfl_xor_sync(0xffffffffu, v, 4);
            v += __shfl_xor_sync(0xffffffffu, v, 2);
            v += __shfl_xor_sync(0xffffffffu, v, 1);
            acc[r][j] = v;
        }
        const int row = rowbase + r;
        if (lane == 0) {
#pragma unroll
            for (int j = 0; j < 16; j++)
                g_Xe[(size_t)row * KPAD + 4096 + j] = __float2half_rn(acc[r][j]);
        }
        if (lane < 6)
            *(uint4*)(g_Xe + (size_t)row * KPAD + 4112 + (size_t)lane * 8) =
                make_uint4(0, 0, 0, 0);
    }
}

// ---------- pack_W: dequant + transpose to We (+ tail at k0=4032) ----------
__global__ void __launch_bounds__(256)
pack_w_kernel(const float* __restrict__ Wq, const float* __restrict__ c1p,
              const float* __restrict__ ck, const float* __restrict__ L2) {
    __shared__ float tile[64 * 65];
    const float c1 = *c1p;
    const int tid = threadIdx.x;
    const int n0 = blockIdx.x * 64, k0 = blockIdx.y * 64;
    const int cidx = tid & 63, ridx = tid >> 6;

#pragma unroll
    for (int ro = 0; ro < 16; ro++) {
        int kk = ro * 4 + ridx;
        size_t g = (size_t)(k0 + kk) * D_OUT + n0 + cidx;
        tile[kk * 65 + cidx] = Wq[g] * c1 * ck[g];
    }
    __syncthreads();
#pragma unroll
    for (int ro = 0; ro < 16; ro++) {
        int nn = ro * 4 + ridx;
        g_We[(size_t)(n0 + nn) * KPAD + k0 + cidx] =
            __float2half_rn(tile[cidx * 65 + nn]);
    }

    // Last k-block also fills the appended-K tail (cols 4096..4159) for its
    // 64 n rows: first 16 cols = L2^T, rest zero.
    if (k0 == D_IN - 64) {
#pragma unroll
        for (int ro = 0; ro < 16; ro++) {
            int idx = ro * 256 + tid;            // 64n x 64k
            int nn = idx >> 6, kk = idx & 63;
            __half v = (kk < 16)
                ? __float2half_rn(L2[(size_t)kk * D_OUT + n0 + nn])
                : __half(0.f);
            g_We[(size_t)(n0 + nn) * KPAD + 4096 + kk] = v;
        }
    }
}

// ------------------------------ GEMM kernel --------------------------------
// Exact R6 loop: 4 warps (2x2), warp tile 64x64, cross-iteration frag prefetch
// with deferred commit_group; sync -> load_frag(1) -> mma(0) ordering.
__global__ void __launch_bounds__(128, 2)
gemm_kernel(float* __restrict__ Y) {
    extern __shared__ char smem[];
    const uint32_t sb = (uint32_t)__cvta_generic_to_shared(smem);
    const int tid = threadIdx.x, wid = tid >> 5, lane = tid & 31;
    const int m0 = blockIdx.y * BM, n0 = blockIdx.x * BN;
    const int wm = wid & 1, wn = wid >> 1;
    const int gid = lane >> 2, tig = lane & 3;

    auto loadA = [&](int kt, int slot) {
        const __half* src = g_Xe + (size_t)m0 * KPAD + (size_t)kt * BK;
        uint32_t base = sb + slot * STAGE;
#pragma unroll
        for (int i = 0; i < 8; i++) {
            int idx = tid + i * 128;
            int r = idx >> 3, c = idx & 7;
            cp16(base + swz((uint32_t)(r * 128 + c * 16)),
                 src + (size_t)r * KPAD + c * 8);
        }
    };
    auto loadB = [&](int kt, int slot) {
        const __half* src = g_We + (size_t)n0 * KPAD + (size_t)kt * BK;
        uint32_t base = sb + slot * STAGE + ABYTES;
#pragma unroll
        for (int i = 0; i < 8; i++) {
            int idx = tid + i * 128;
            int r = idx >> 3, c = idx & 7;
            cp16(base + swz((uint32_t)(r * 128 + c * 16)),
                 src + (size_t)r * KPAD + c * 8);
        }
    };

    float acc[4][8][4];
#pragma unroll
    for (int t = 0; t < 4; t++)
#pragma unroll
        for (int n = 0; n < 8; n++)
#pragma unroll
            for (int j = 0; j < 4; j++) acc[t][n][j] = 0.f;

#pragma unroll
    for (int s = 0; s < S - 1; s++) { loadA(s, s); loadB(s, s); CP_COMMIT(); }

    const uint32_t a_row = (uint32_t)(wm * 64 + (lane & 15));
    const uint32_t a_chk = (uint32_t)(lane >> 4);
    const uint32_t b_row = (uint32_t)(wn * 64 + ((lane >> 4) & 1) * 8 + (lane & 7));
    const uint32_t b_chk = (uint32_t)((lane >> 3) & 1);

    uint32_t af[2][4][4];
    uint32_t bf[2][8][2];

    auto load_frag = [&](int buf, uint32_t abase, int ks) {
        const uint32_t bbase = abase + ABYTES;
#pragma unroll
        for (int t = 0; t < 4; t++) {
            uint32_t off = (a_row + t * 16) * 128 + (a_chk + ks * 2) * 16;
            LDSM4(af[buf][t], abase + swz(off));
        }
#pragma unroll
        for (int g = 0; g < 4; g++) {
            uint32_t off = (b_row + g * 16) * 128 + (b_chk + ks * 2) * 16;
            uint32_t r[4];
            LDSM4(r, bbase + swz(off));
            bf[buf][2 * g][0] = r[0];     bf[buf][2 * g][1] = r[1];
            bf[buf][2 * g + 1][0] = r[2]; bf[buf][2 * g + 1][1] = r[3];
        }
    };
    auto mma_block = [&](int buf) {
#pragma unroll
        for (int t = 0; t < 4; t++)
#pragma unroll
            for (int n = 0; n < 8; n++)
                MMA16816(acc[t][n], af[buf][t], bf[buf][n]);
    };

    // Wait stage 0 (leave stage 1 in flight), prefetch its ks=0 fragments.
    CP_WAIT(1);
    __syncthreads();
    load_frag(0, sb + 0 * STAGE, 0);

    for (int kt = 0; kt < KT; kt++) {
        const uint32_t abase = sb + (kt % S) * STAGE;
        // Barrier: about to overwrite slot (kt+2)%S == (kt-1)%S. All reads of
        // stage kt-1 (and the prefetch read of stage kt) happened before here.
        __syncthreads();

        load_frag(1, abase, 1);          // ks=1 frags first (critical path)
        mma_block(0);                    // ks=0 (prefetched)

        if (kt + 2 < KT) {               // issue next stage UNCOMMITTED
            loadA(kt + 2, (kt + 2) % S);
            loadB(kt + 2, (kt + 2) % S);
        }

        load_frag(0, abase, 2);
        mma_block(1);                    // ks=1

        load_frag(1, abase, 3);
        mma_block(0);                    // ks=2

        if (kt + 1 < KT) {
            CP_WAIT(0);                  // drains stage kt+1 only (kt+2 uncommitted)
            load_frag(0, sb + ((kt + 1) % S) * STAGE, 0);   // prefetch next ks=0
        }
        mma_block(1);                    // ks=3
        CP_COMMIT();                     // name stage kt+2's group
    }

    // Epilogue: direct float2 stores
#pragma unroll
    for (int t = 0; t < 4; t++) {
        const int r0 = m0 + wm * 64 + t * 16 + gid;
        float* y0 = Y + (size_t)r0 * D_OUT + n0 + wn * 64 + tig * 2;
        float* y1 = y0 + (size_t)8 * D_OUT;
#pragma unroll
        for (int n = 0; n < 8; n++) {
            *(float2*)(y0 + n * 8) = make_float2(acc[t][n][0], acc[t][n][1]);
            *(float2*)(y1 + n * 8) = make_float2(acc[t][n][2], acc[t][n][3]);
        }
    }
}

// ------------------------------- launcher ----------------------------------
extern "C" void kernel_launch(void* const* d_in, const int* in_sizes, int n_in,
                              void* d_out, int out_size) {
    const float* X  = (const float*)d_in[0];
    const float* Wq = (const float*)d_in[1];
    const float* c1 = (const float*)d_in[2];
    const float* ck = (const float*)d_in[3];
    const float* L1 = (const float*)d_in[4];
    const float* L2 = (const float*)d_in[5];
    float* Y = (float*)d_out;

    cudaFuncSetAttribute(gemm_kernel, cudaFuncAttributeMaxDynamicSharedMemorySize, SMEM_SZ);

    pack_x_kernel<<<NROWS / 32, 256>>>(X, L1);
    pack_w_kernel<<<dim3(D_OUT / 64, D_IN / 64), 256>>>(Wq, c1, ck, L2);
    gemm_kernel<<<dim3(D_OUT / BN, NROWS / BM), 128, SMEM_SZ>>>(Y);
}